// round 1
// baseline (speedup 1.0000x reference)
#include <cuda_runtime.h>
#include <cstdint>

#define BATCH 16
#define CIN   256
#define HH    80
#define WW    80
#define CMID  64
#define CENC  100
#define K2T   25
#define HO    160
#define WO    160
#define EPS   1e-5f

// Scratch (device globals -- allocation-free)
__device__ __align__(16) float g_mid[(size_t)BATCH * CMID * HH * WW];      // 26.2 MB
__device__ __align__(16) float g_wm[(size_t)BATCH * K2T * HO * WO];        // 41 MB

// ---------------------------------------------------------------------------
// K1: 1x1 conv (256->64) + BN + SiLU.  GEMM per batch: [64 x 256] x [256 x 6400]
// Block: 64 output channels x 64 pixels. 256 threads, 4x4 micro-tile each.
// ---------------------------------------------------------------------------
__global__ __launch_bounds__(256) void k1_comp(
    const float* __restrict__ X, const float* __restrict__ Wc,
    const float* __restrict__ g1, const float* __restrict__ b1,
    const float* __restrict__ m1, const float* __restrict__ v1)
{
    const int b  = blockIdx.y;
    const int p0 = blockIdx.x * 64;

    __shared__ __align__(16) float Xs[32][68];   // [k][n]
    __shared__ __align__(16) float Ws[32][68];   // [k][m]

    const int tx = threadIdx.x & 15;   // N dim
    const int ty = threadIdx.x >> 4;   // M dim

    float acc[4][4];
#pragma unroll
    for (int i = 0; i < 4; i++)
#pragma unroll
        for (int j = 0; j < 4; j++) acc[i][j] = 0.f;

    const float* Xb = X + (size_t)b * CIN * (HH * WW) + p0;

    for (int k0 = 0; k0 < CIN; k0 += 32) {
        // Load X tile: 32 k x 64 n (coalesced: nn fastest)
        for (int i = threadIdx.x; i < 2048; i += 256) {
            int kk = i >> 6, nn = i & 63;
            Xs[kk][nn] = Xb[(size_t)(k0 + kk) * (HH * WW) + nn];
        }
        // Load W tile: kk fastest in global -> coalesced
        for (int i = threadIdx.x; i < 2048; i += 256) {
            int m = i >> 5, kk = i & 31;
            Ws[kk][m] = Wc[m * CIN + k0 + kk];
        }
        __syncthreads();
#pragma unroll
        for (int kk = 0; kk < 32; kk++) {
            float4 a  = *(const float4*)&Ws[kk][ty * 4];
            float4 bb = *(const float4*)&Xs[kk][tx * 4];
            float av[4] = {a.x, a.y, a.z, a.w};
            float bv[4] = {bb.x, bb.y, bb.z, bb.w};
#pragma unroll
            for (int i = 0; i < 4; i++)
#pragma unroll
                for (int j = 0; j < 4; j++) acc[i][j] += av[i] * bv[j];
        }
        __syncthreads();
    }

    // BN + SiLU + write (float4 stores)
#pragma unroll
    for (int i = 0; i < 4; i++) {
        int m = ty * 4 + i;
        float is = g1[m] * rsqrtf(v1[m] + EPS);
        float bi = b1[m] - m1[m] * is;
        float4 o;
        float ov[4];
#pragma unroll
        for (int j = 0; j < 4; j++) {
            float v = acc[i][j] * is + bi;
            ov[j] = v / (1.f + __expf(-v));
        }
        o.x = ov[0]; o.y = ov[1]; o.z = ov[2]; o.w = ov[3];
        *(float4*)&g_mid[((size_t)(b * CMID + m)) * (HH * WW) + p0 + tx * 4] = o;
    }
}

// ---------------------------------------------------------------------------
// K2: 3x3 conv (64->100) + BN + PixelShuffle(2) + softmax(25) -> g_wm
// Tile: 16(h) x 8(w) low-res pixels. 256 threads = 64 pixel-pairs x 4 subpix q.
// Thread q owns channels c = 4*kk + q, which are exactly the 25 softmax lanes
// for subpixel (si,sj) = (q>>1, q&1).
// ---------------------------------------------------------------------------
__global__ __launch_bounds__(256) void k2_enc(
    const float* __restrict__ We,
    const float* __restrict__ g2, const float* __restrict__ b2,
    const float* __restrict__ m2, const float* __restrict__ v2)
{
    const int b  = blockIdx.z;
    const int h0 = blockIdx.y * 16;
    const int w0 = blockIdx.x * 8;

    __shared__ float Ms[8][18][10];                       // input chunk tile
    __shared__ __align__(16) float Wk[8][4][25][12];      // weights [ic][q][kk][tap(pad12)]
    __shared__ float scs[100], bis[100];

    const int tid = threadIdx.x;
    if (tid < 100) {
        float is = g2[tid] * rsqrtf(v2[tid] + EPS);
        scs[tid] = is;
        bis[tid] = b2[tid] - m2[tid] * is;
    }

    const int pp = tid & 63;       // pixel-pair id
    const int q  = tid >> 6;       // subpixel 0..3
    const int hA = pp >> 3, wA = pp & 7;
    const int hB = hA + 8;

    float acc0[25], acc1[25];
#pragma unroll
    for (int kk = 0; kk < 25; kk++) { acc0[kk] = 0.f; acc1[kk] = 0.f; }

    for (int c0 = 0; c0 < CMID; c0 += 8) {
        __syncthreads();
        // input tile: 8 ch x 18 x 10 (rows h0-1..h0+16, cols w0-1..w0+8)
        for (int i = tid; i < 1440; i += 256) {
            int ic = i / 180, r = i % 180, dy = r / 10, dx = r % 10;
            int gh = h0 + dy - 1, gw = w0 + dx - 1;
            float val = 0.f;
            if (gh >= 0 && gh < HH && gw >= 0 && gw < WW)
                val = g_mid[(((size_t)(b * CMID + c0 + ic)) * HH + gh) * WW + gw];
            Ms[ic][dy][dx] = val;
        }
        // weight chunk: 8 ic x 100 c x 9 taps
        for (int i = tid; i < 7200; i += 256) {
            int ic = i / 900, r = i % 900, c = r / 9, tap = r % 9;
            Wk[ic][c & 3][c >> 2][tap] = We[(size_t)c * (CMID * 9) + (c0 + ic) * 9 + tap];
        }
        __syncthreads();

#pragma unroll 1
        for (int ic = 0; ic < 8; ic++) {
            float xa[9], xb[9];
#pragma unroll
            for (int t = 0; t < 9; t++) {
                int dy = t / 3, dx = t % 3;
                xa[t] = Ms[ic][hA + dy][wA + dx];
                xb[t] = Ms[ic][hB + dy][wA + dx];
            }
            const float* wp = &Wk[ic][q][0][0];
#pragma unroll
            for (int kk = 0; kk < 25; kk++) {
                float4 wa = *(const float4*)(wp + kk * 12);
                float4 wb = *(const float4*)(wp + kk * 12 + 4);
                float w8  = wp[kk * 12 + 8];
                acc0[kk] += wa.x * xa[0] + wa.y * xa[1] + wa.z * xa[2] + wa.w * xa[3]
                          + wb.x * xa[4] + wb.y * xa[5] + wb.z * xa[6] + wb.w * xa[7]
                          + w8  * xa[8];
                acc1[kk] += wa.x * xb[0] + wa.y * xb[1] + wa.z * xb[2] + wa.w * xb[3]
                          + wb.x * xb[4] + wb.y * xb[5] + wb.z * xb[6] + wb.w * xb[7]
                          + w8  * xb[8];
            }
        }
    }

    // BN + softmax over the 25 lanes, write to g_wm
    const int si = q >> 1, sj = q & 1;
#pragma unroll
    for (int p = 0; p < 2; p++) {
        float* ac = p ? acc1 : acc0;
        int hh = p ? hB : hA;
        float mx = -1e30f;
#pragma unroll
        for (int kk = 0; kk < 25; kk++) {
            float v = ac[kk] * scs[4 * kk + q] + bis[4 * kk + q];
            ac[kk] = v;
            mx = fmaxf(mx, v);
        }
        float s = 0.f;
#pragma unroll
        for (int kk = 0; kk < 25; kk++) {
            float e = __expf(ac[kk] - mx);
            ac[kk] = e;
            s += e;
        }
        float inv = 1.f / s;
        int y = 2 * (h0 + hh) + si;
        int x = 2 * (w0 + wA) + sj;
#pragma unroll
        for (int kk = 0; kk < 25; kk++)
            g_wm[(((size_t)(b * K2T + kk)) * HO + y) * WO + x] = ac[kk] * inv;
    }
}

// ---------------------------------------------------------------------------
// K3: CARAFE reassembly.
// out[b,c,2h+si,2w+sj] = sum_{ki,kj} W[b,ki*5+kj,2h+si,2w+sj] * X[b,c,h+ki-2,w+kj-2]
// Block: one 8x8 low-res tile; loops over 8 groups of 32 channels (W read once).
// 256 threads = 64 pixels x 4 channel-subgroups of 8.
// ---------------------------------------------------------------------------
__global__ __launch_bounds__(256) void k3_carafe(
    const float* __restrict__ X, float* __restrict__ out)
{
    const int b = blockIdx.y;
    const int h0 = (blockIdx.x / 10) * 8;
    const int w0 = (blockIdx.x % 10) * 8;

    __shared__ __align__(16) float Ws4[25][64][4];   // [kidx][px][subpix]
    __shared__ float Xs[32][12][12];

    const int tid = threadIdx.x;

    // Load softmaxed weights for this tile once (float2-coalesced)
    for (int i = tid; i < 3200; i += 256) {
        int kk = i / 128, r = i % 128, si = r >> 6, p = r & 63;
        int h = p >> 3, w = p & 7;
        int y = 2 * (h0 + h) + si, x = 2 * (w0 + w);
        float2 v = *(const float2*)&g_wm[(((size_t)(b * K2T + kk)) * HO + y) * WO + x];
        Ws4[kk][p][si * 2 + 0] = v.x;
        Ws4[kk][p][si * 2 + 1] = v.y;
    }

    const int px = tid & 63, g = tid >> 6;
    const int h = px >> 3, w = px & 7;

    for (int cg = 0; cg < 8; cg++) {
        const int cbase = cg * 32;
        __syncthreads();   // protects Ws4 (first iter) and Xs reuse
        for (int i = tid; i < 4608; i += 256) {
            int cc = i / 144, r = i % 144, dy = r / 12, dx = r % 12;
            int gh = h0 + dy - 2, gw = w0 + dx - 2;
            float val = 0.f;
            if (gh >= 0 && gh < HH && gw >= 0 && gw < WW)
                val = X[(((size_t)(b * CIN + cbase + cc)) * HH + gh) * WW + gw];
            Xs[cc][dy][dx] = val;
        }
        __syncthreads();

        float acc[8][4];
#pragma unroll
        for (int cc = 0; cc < 8; cc++)
#pragma unroll
            for (int s = 0; s < 4; s++) acc[cc][s] = 0.f;

#pragma unroll
        for (int t = 0; t < 25; t++) {
            int ki = t / 5, kj = t % 5;
            float4 wv = *(const float4*)&Ws4[t][px][0];
#pragma unroll
            for (int cc = 0; cc < 8; cc++) {
                float xv = Xs[g * 8 + cc][h + ki][w + kj];
                acc[cc][0] += wv.x * xv;
                acc[cc][1] += wv.y * xv;
                acc[cc][2] += wv.z * xv;
                acc[cc][3] += wv.w * xv;
            }
        }

        // float2 stores: pairs (sj=0,1) are x-adjacent -> fully coalesced
#pragma unroll
        for (int cc = 0; cc < 8; cc++) {
            int c = cbase + g * 8 + cc;
#pragma unroll
            for (int si = 0; si < 2; si++) {
                int y = 2 * (h0 + h) + si, x = 2 * (w0 + w);
                float2 v;
                v.x = acc[cc][si * 2 + 0];
                v.y = acc[cc][si * 2 + 1];
                *(float2*)&out[(((size_t)(b * CIN + c)) * HO + y) * WO + x] = v;
            }
        }
    }
}

// ---------------------------------------------------------------------------
extern "C" void kernel_launch(void* const* d_in, const int* in_sizes, int n_in,
                              void* d_out, int out_size)
{
    const float* X  = (const float*)d_in[0];
    const float* Wc = (const float*)d_in[1];
    const float* g1 = (const float*)d_in[2];
    const float* b1 = (const float*)d_in[3];
    const float* m1 = (const float*)d_in[4];
    const float* v1 = (const float*)d_in[5];
    const float* We = (const float*)d_in[6];
    const float* g2 = (const float*)d_in[7];
    const float* b2 = (const float*)d_in[8];
    const float* m2 = (const float*)d_in[9];
    const float* v2 = (const float*)d_in[10];
    float* out = (float*)d_out;

    k1_comp<<<dim3(100, BATCH), 256>>>(X, Wc, g1, b1, m1, v1);
    k2_enc<<<dim3(10, 5, BATCH), 256>>>(We, g2, b2, m2, v2);
    k3_carafe<<<dim3(100, BATCH), 256>>>(X, out);
}

// round 3
// speedup vs baseline: 1.5760x; 1.5760x over previous
#include <cuda_runtime.h>
#include <cuda_bf16.h>
#include <cstdint>

#define BATCH 16
#define CIN   256
#define HH    80
#define WW    80
#define CMID  64
#define K2T   25
#define HO    160
#define WO    160
#define EPS   1e-5f

// ---------------------------------------------------------------------------
// Device scratch (allocation-free)
// ---------------------------------------------------------------------------
__device__ __align__(16) __nv_bfloat16 g_midT_hi[(size_t)BATCH * 6400 * 64]; // [b][pix][c]
__device__ __align__(16) __nv_bfloat16 g_midT_lo[(size_t)BATCH * 6400 * 64];
// per-tap weights, n-major: [tap][split][c(112)][ic(72)] bf16
__device__ __align__(16) __nv_bfloat16 g_weP[9 * 2 * 112 * 72];
__device__ __align__(16) float g_wm[(size_t)BATCH * K2T * HO * WO];

__device__ __forceinline__ uint32_t smem_u32(const void* p) {
    uint32_t a;
    asm("{ .reg .u64 t; cvta.to.shared.u64 t, %1; cvt.u32.u64 %0, t; }" : "=r"(a) : "l"(p));
    return a;
}
__device__ __forceinline__ void ldsm_x4(uint32_t& r0, uint32_t& r1, uint32_t& r2, uint32_t& r3,
                                        uint32_t addr) {
    asm volatile("ldmatrix.sync.aligned.m8n8.x4.shared.b16 {%0,%1,%2,%3}, [%4];"
                 : "=r"(r0), "=r"(r1), "=r"(r2), "=r"(r3) : "r"(addr));
}
__device__ __forceinline__ void ldsm_x2(uint32_t& r0, uint32_t& r1, uint32_t addr) {
    asm volatile("ldmatrix.sync.aligned.m8n8.x2.shared.b16 {%0,%1}, [%2];"
                 : "=r"(r0), "=r"(r1) : "r"(addr));
}
__device__ __forceinline__ void mma16816(float* d, const uint32_t* a, uint32_t b0, uint32_t b1) {
    asm volatile(
        "mma.sync.aligned.m16n8k16.row.col.f32.bf16.bf16.f32 "
        "{%0,%1,%2,%3}, {%4,%5,%6,%7}, {%8,%9}, {%0,%1,%2,%3};"
        : "+f"(d[0]), "+f"(d[1]), "+f"(d[2]), "+f"(d[3])
        : "r"(a[0]), "r"(a[1]), "r"(a[2]), "r"(a[3]), "r"(b0), "r"(b1));
}

// ---------------------------------------------------------------------------
// K0: weights -> [tap][split][c pad 112][ic pad 72] bf16 split
// ---------------------------------------------------------------------------
__global__ __launch_bounds__(256) void k0_wprep(const float* __restrict__ We) {
    int i = blockIdx.x * 256 + threadIdx.x;
    if (i >= 9 * 2 * 112 * 72) return;
    int tap = i / 16128, r = i % 16128;
    int s = r / 8064; r %= 8064;
    int c = r / 72, ic = r % 72;
    float v = (c < 100 && ic < 64) ? We[c * 576 + ic * 9 + tap] : 0.f;
    __nv_bfloat16 hi = __float2bfloat16(v);
    g_weP[i] = s ? __float2bfloat16(v - __bfloat162float(hi)) : hi;
}

// ---------------------------------------------------------------------------
// K1: 1x1 conv (256->64) + BN + SiLU -> bf16 split, pixel-major [b][pix][c]
// ---------------------------------------------------------------------------
__global__ __launch_bounds__(256) void k1_comp(
    const float* __restrict__ X, const float* __restrict__ Wc,
    const float* __restrict__ g1, const float* __restrict__ b1,
    const float* __restrict__ m1, const float* __restrict__ v1)
{
    const int b  = blockIdx.y;
    const int p0 = blockIdx.x * 64;

    __shared__ __align__(16) float Xs[32][68];
    __shared__ __align__(16) float Ws[32][68];
    __shared__ __align__(16) __nv_bfloat16 s_hi[64][72];
    __shared__ __align__(16) __nv_bfloat16 s_lo[64][72];

    const int tx = threadIdx.x & 15;
    const int ty = threadIdx.x >> 4;

    float acc[4][4];
#pragma unroll
    for (int i = 0; i < 4; i++)
#pragma unroll
        for (int j = 0; j < 4; j++) acc[i][j] = 0.f;

    const float* Xb = X + (size_t)b * CIN * (HH * WW) + p0;

    for (int k0 = 0; k0 < CIN; k0 += 32) {
        for (int i = threadIdx.x; i < 2048; i += 256) {
            int kk = i >> 6, nn = i & 63;
            Xs[kk][nn] = Xb[(size_t)(k0 + kk) * (HH * WW) + nn];
        }
        for (int i = threadIdx.x; i < 2048; i += 256) {
            int m = i >> 5, kk = i & 31;
            Ws[kk][m] = Wc[m * CIN + k0 + kk];
        }
        __syncthreads();
#pragma unroll
        for (int kk = 0; kk < 32; kk++) {
            float4 a  = *(const float4*)&Ws[kk][ty * 4];
            float4 bb = *(const float4*)&Xs[kk][tx * 4];
            float av[4] = {a.x, a.y, a.z, a.w};
            float bv[4] = {bb.x, bb.y, bb.z, bb.w};
#pragma unroll
            for (int i = 0; i < 4; i++)
#pragma unroll
                for (int j = 0; j < 4; j++) acc[i][j] += av[i] * bv[j];
        }
        __syncthreads();
    }

#pragma unroll
    for (int i = 0; i < 4; i++) {
        int m = ty * 4 + i;
        float is = g1[m] * rsqrtf(v1[m] + EPS);
        float bi = b1[m] - m1[m] * is;
#pragma unroll
        for (int j = 0; j < 4; j++) {
            float v = acc[i][j] * is + bi;
            float sv = v / (1.f + __expf(-v));
            __nv_bfloat16 hi = __float2bfloat16(sv);
            s_hi[tx * 4 + j][m] = hi;
            s_lo[tx * 4 + j][m] = __float2bfloat16(sv - __bfloat162float(hi));
        }
    }
    __syncthreads();

    for (int i = threadIdx.x; i < 1024; i += 256) {
        int bufi = i >> 9, r = (i >> 3) & 63, ch = i & 7;
        uint4 v = bufi ? *(const uint4*)&s_lo[r][ch * 8] : *(const uint4*)&s_hi[r][ch * 8];
        uint4* dst = (uint4*)(bufi ? g_midT_lo : g_midT_hi);
        dst[(size_t)(b * 6400 + p0 + r) * 8 + ch] = v;
    }
}

// ---------------------------------------------------------------------------
// K2: 3x3 conv (64->100) via mma.sync bf16 split-3 + BN + shuffle + softmax
//   CTA tile: 16x8 low-res pixels (128). M=128 px, N=112 ch, K=9 taps x 64 ic.
//   Warps: 4 (M) x 2 (N): each 32 px x 56 ch.
// ---------------------------------------------------------------------------
// dynamic smem (bytes)
#define SM_ACT_HI 0            // 180 rows * 144B
#define SM_ACT_LO 25920
#define SM_W      51840        // [split][112][72] bf16 = 32256B
#define SM_SCS    84096
#define SM_BIS    84496
#define SM_TOTAL  84992
#define DT_STRIDE 122          // floats

__global__ __launch_bounds__(256, 2)
void k2_enc(const float* __restrict__ g2, const float* __restrict__ b2,
            const float* __restrict__ m2, const float* __restrict__ v2)
{
    extern __shared__ __align__(16) char sm[];
    const int b  = blockIdx.z;
    const int h0 = blockIdx.y * 16;
    const int w0 = blockIdx.x * 8;
    const int tid = threadIdx.x;
    const int wid = tid >> 5;
    const int lan = tid & 31;
    const uint32_t smb = smem_u32(sm);

    if (tid < 100) {
        float is = g2[tid] * rsqrtf(v2[tid] + EPS);
        ((float*)(sm + SM_SCS))[tid] = is;
        ((float*)(sm + SM_BIS))[tid] = b2[tid] - m2[tid] * is;
    }

    // stage 18x10 activation tile (hi+lo): row r -> 64ch, 144B stride
    for (int k = tid; k < 2880; k += 256) {
        int bufi = (k >= 1440);
        int r = bufi ? k - 1440 : k;
        int row = r >> 3, ch = r & 7;
        int y = row / 10, x = row - y * 10;
        int gh = h0 + y - 1, gw = w0 + x - 1;
        uint4 v = make_uint4(0, 0, 0, 0);
        if (gh >= 0 && gh < HH && gw >= 0 && gw < WW) {
            const uint4* src = (const uint4*)(bufi ? g_midT_lo : g_midT_hi);
            v = src[(size_t)(b * 6400 + gh * WW + gw) * 8 + ch];
        }
        *(uint4*)(sm + (bufi ? SM_ACT_LO : SM_ACT_HI) + row * 144 + (ch << 4)) = v;
    }

    const int warpm = wid & 3;   // M: 32 px
    const int warpn = wid >> 2;  // N: 56 ch

    float acc[2][7][4];
#pragma unroll
    for (int mb = 0; mb < 2; mb++)
#pragma unroll
        for (int nb = 0; nb < 7; nb++)
#pragma unroll
            for (int j = 0; j < 4; j++) acc[mb][nb][j] = 0.f;

    // per-lane A row (pixel) and B row (channel) bases
    const int pA0 = warpm * 32 + (lan & 15);            // mb adds +16
    const int pyA0 = pA0 >> 3, pxA0 = pA0 & 7;
    const uint32_t a_half = (uint32_t)((lan >> 4) << 4);  // +16B for k8..15
    const int cB = warpn * 56 + (lan & 7);
    const uint32_t b_half = (uint32_t)(((lan >> 3) & 1) << 4);
    const uint32_t wb_hi = smb + SM_W + (uint32_t)cB * 144 + b_half;
    const uint32_t wb_lo = wb_hi + 16128;

    for (int tap = 0; tap < 9; tap++) {
        const int dy = tap / 3, dx = tap - dy * 3;
        __syncthreads();   // previous tap's ldmatrix done; weights reusable
        // load tap weights: 2016 uint4, contiguous
        {
            const uint4* gsrc = (const uint4*)g_weP + tap * 2016;
            for (int k = tid; k < 2016; k += 256)
                *(uint4*)(sm + SM_W + (k << 4)) = gsrc[k];
        }
        __syncthreads();

        // A row byte offsets for this tap (per mb)
        uint32_t arow0 = (uint32_t)(((pyA0 + dy) * 10 + pxA0 + dx) * 144) + a_half;
        uint32_t arow1 = (uint32_t)(((((pA0 + 16) >> 3) + dy) * 10 + ((pA0 + 16) & 7) + dx) * 144) + a_half;

#pragma unroll
        for (int ks = 0; ks < 4; ks++) {
            const uint32_t ko = (uint32_t)(ks << 5);
            uint32_t Ah[2][4], Al[2][4];
            ldsm_x4(Ah[0][0], Ah[0][1], Ah[0][2], Ah[0][3], smb + SM_ACT_HI + arow0 + ko);
            ldsm_x4(Ah[1][0], Ah[1][1], Ah[1][2], Ah[1][3], smb + SM_ACT_HI + arow1 + ko);
            ldsm_x4(Al[0][0], Al[0][1], Al[0][2], Al[0][3], smb + SM_ACT_LO + arow0 + ko);
            ldsm_x4(Al[1][0], Al[1][1], Al[1][2], Al[1][3], smb + SM_ACT_LO + arow1 + ko);
#pragma unroll
            for (int nb = 0; nb < 7; nb++) {
                uint32_t bh0, bh1, bl0, bl1;
                ldsm_x2(bh0, bh1, wb_hi + (uint32_t)(nb * 1152) + ko);
                ldsm_x2(bl0, bl1, wb_lo + (uint32_t)(nb * 1152) + ko);
#pragma unroll
                for (int mb = 0; mb < 2; mb++) {
                    mma16816(acc[mb][nb], Ah[mb], bh0, bh1);
                    mma16816(acc[mb][nb], Ah[mb], bl0, bl1);
                    mma16816(acc[mb][nb], Al[mb], bh0, bh1);
                }
            }
        }
    }
    __syncthreads();

    // store D fragments to smem Dt[p][c] (reuses act+weight region)
    float* Dt = (float*)sm;
#pragma unroll
    for (int mb = 0; mb < 2; mb++) {
        int r = warpm * 32 + mb * 16 + (lan >> 2);
#pragma unroll
        for (int nb = 0; nb < 7; nb++) {
            int c = warpn * 56 + nb * 8 + 2 * (lan & 3);
            *(float2*)&Dt[r * DT_STRIDE + c] = make_float2(acc[mb][nb][0], acc[mb][nb][1]);
            *(float2*)&Dt[(r + 8) * DT_STRIDE + c] = make_float2(acc[mb][nb][2], acc[mb][nb][3]);
        }
    }
    __syncthreads();

    // BN + softmax over 25 taps per (pixel, subpixel)
    const float* scs = (const float*)(sm + SM_SCS);
    const float* bis = (const float*)(sm + SM_BIS);
    for (int it = tid; it < 512; it += 256) {
        int p = it >> 2, q = it & 3;
        float v[25];
        float mx = -1e30f;
#pragma unroll
        for (int k = 0; k < 25; k++) {
            int m = (k << 2) + q;
            float x = Dt[p * DT_STRIDE + m] * scs[m] + bis[m];
            v[k] = x;
            mx = fmaxf(mx, x);
        }
        float s = 0.f;
#pragma unroll
        for (int k = 0; k < 25; k++) {
            float e = __expf(v[k] - mx);
            v[k] = e;
            s += e;
        }
        float inv = 1.f / s;
        int y = 2 * (h0 + (p >> 3)) + (q >> 1);
        int x = 2 * (w0 + (p & 7)) + (q & 1);
#pragma unroll
        for (int k = 0; k < 25; k++)
            g_wm[(((size_t)(b * K2T + k)) * HO + y) * WO + x] = v[k] * inv;
    }
}

// ---------------------------------------------------------------------------
// K3: CARAFE reassembly (unchanged)
// ---------------------------------------------------------------------------
__global__ __launch_bounds__(256) void k3_carafe(
    const float* __restrict__ X, float* __restrict__ out)
{
    const int b = blockIdx.y;
    const int h0 = (blockIdx.x / 10) * 8;
    const int w0 = (blockIdx.x % 10) * 8;

    __shared__ __align__(16) float Ws4[25][64][4];
    __shared__ float Xs[32][12][12];

    const int tid = threadIdx.x;

    for (int i = tid; i < 3200; i += 256) {
        int kk = i / 128, r = i % 128, si = r >> 6, p = r & 63;
        int h = p >> 3, w = p & 7;
        int y = 2 * (h0 + h) + si, x = 2 * (w0 + w);
        float2 v = *(const float2*)&g_wm[(((size_t)(b * K2T + kk)) * HO + y) * WO + x];
        Ws4[kk][p][si * 2 + 0] = v.x;
        Ws4[kk][p][si * 2 + 1] = v.y;
    }

    const int px = tid & 63, g = tid >> 6;
    const int h = px >> 3, w = px & 7;

    for (int cg = 0; cg < 8; cg++) {
        const int cbase = cg * 32;
        __syncthreads();
        for (int i = tid; i < 4608; i += 256) {
            int cc = i / 144, r = i % 144, dy = r / 12, dx = r % 12;
            int gh = h0 + dy - 2, gw = w0 + dx - 2;
            float val = 0.f;
            if (gh >= 0 && gh < HH && gw >= 0 && gw < WW)
                val = X[(((size_t)(b * CIN + cbase + cc)) * HH + gh) * WW + gw];
            Xs[cc][dy][dx] = val;
        }
        __syncthreads();

        float acc[8][4];
#pragma unroll
        for (int cc = 0; cc < 8; cc++)
#pragma unroll
            for (int s = 0; s < 4; s++) acc[cc][s] = 0.f;

#pragma unroll
        for (int t = 0; t < 25; t++) {
            int ki = t / 5, kj = t % 5;
            float4 wv = *(const float4*)&Ws4[t][px][0];
#pragma unroll
            for (int cc = 0; cc < 8; cc++) {
                float xv = Xs[g * 8 + cc][h + ki][w + kj];
                acc[cc][0] += wv.x * xv;
                acc[cc][1] += wv.y * xv;
                acc[cc][2] += wv.z * xv;
                acc[cc][3] += wv.w * xv;
            }
        }

#pragma unroll
        for (int cc = 0; cc < 8; cc++) {
            int c = cbase + g * 8 + cc;
#pragma unroll
            for (int si = 0; si < 2; si++) {
                int y = 2 * (h0 + h) + si, x = 2 * (w0 + w);
                float2 v;
                v.x = acc[cc][si * 2 + 0];
                v.y = acc[cc][si * 2 + 1];
                *(float2*)&out[(((size_t)(b * CIN + c)) * HO + y) * WO + x] = v;
            }
        }
    }
}

// ---------------------------------------------------------------------------
extern "C" void kernel_launch(void* const* d_in, const int* in_sizes, int n_in,
                              void* d_out, int out_size)
{
    const float* X  = (const float*)d_in[0];
    const float* Wc = (const float*)d_in[1];
    const float* g1 = (const float*)d_in[2];
    const float* b1 = (const float*)d_in[3];
    const float* m1 = (const float*)d_in[4];
    const float* v1 = (const float*)d_in[5];
    const float* We = (const float*)d_in[6];
    const float* g2 = (const float*)d_in[7];
    const float* b2 = (const float*)d_in[8];
    const float* m2 = (const float*)d_in[9];
    const float* v2 = (const float*)d_in[10];
    float* out = (float*)d_out;

    cudaFuncSetAttribute(k2_enc, cudaFuncAttributeMaxDynamicSharedMemorySize, SM_TOTAL);

    k0_wprep<<<568, 256>>>(We);
    k1_comp<<<dim3(100, BATCH), 256>>>(X, Wc, g1, b1, m1, v1);
    k2_enc<<<dim3(10, 5, BATCH), 256, SM_TOTAL>>>(g2, b2, m2, v2);
    k3_carafe<<<dim3(100, BATCH), 256>>>(X, out);
}